// round 3
// baseline (speedup 1.0000x reference)
#include <cuda_runtime.h>
#include <cuda_bf16.h>
#include <cstdint>
#include <cstddef>

typedef unsigned long long u64t;

#define Bb 32
#define Tt 2048
#define Ff 128
#define Hh 512
#define WINW 80          // words per K-window
#define WPAD 84          // padded stride (bank stagger: 84*4B -> 8 windows hit distinct banks)
#define BUFW (8*WPAD)    // 672 words per (parity,batch) K-vector [h(512) | x(128)]

__device__ __forceinline__ uint32_t smem_u32(const void* p){
  uint32_t a; asm("{ .reg .u64 t; cvta.to.shared.u64 t, %1; cvt.u32.u64 %0, t; }" : "=r"(a) : "l"(p)); return a;
}
__device__ __forceinline__ uint32_t mapa_u32(uint32_t a, uint32_t r){
  uint32_t d; asm("mapa.shared::cluster.u32 %0, %1, %2;" : "=r"(d) : "r"(a), "r"(r)); return d;
}
__device__ __forceinline__ void stc64(uint32_t a, u64t v){
  asm volatile("st.shared::cluster.u64 [%0], %1;" :: "r"(a), "l"(v) : "memory");
}
__device__ __forceinline__ void stc32(uint32_t a, float v){
  asm volatile("st.shared::cluster.f32 [%0], %1;" :: "r"(a), "f"(v) : "memory");
}
__device__ __forceinline__ void cluster_sync_all(){
  asm volatile("barrier.cluster.arrive.aligned;" ::: "memory");
  asm volatile("barrier.cluster.wait.aligned;" ::: "memory");
}
#define FMA2(d,a,b,c) asm("fma.rn.f32x2 %0, %1, %2, %3;" : "=l"(d) : "l"(a), "l"(b), "l"(c))
__device__ __forceinline__ float2 unpack2(u64t v){
  float2 r; asm("mov.b64 {%0,%1}, %2;" : "=f"(r.x), "=f"(r.y) : "l"(v)); return r;
}
__device__ __forceinline__ u64t pack2(float lo, float hi){
  u64t r; asm("mov.b64 %0, {%1,%2};" : "=l"(r) : "f"(lo), "f"(hi)); return r;
}

// 16 clusters of 8 CTAs; cluster c handles batches 2c, 2c+1.
// CTA (rank) holds rows [rank*64, rank*64+64) of W = [W_hh | W_ih] (640 cols) in registers.
// Thread (rs, q8), rs=tid>>3 in 0..31, q8=tid&7: rows 2rs,2rs+1; K-window [q8*80, q8*80+80).
__global__ void __launch_bounds__(256,1) __cluster_dims__(8,1,1)
rnn_enc_kernel(const float* __restrict__ x, const int* __restrict__ lengths,
               const float* __restrict__ W_ih, const float* __restrict__ W_hh,
               const float* __restrict__ b_ih, const float* __restrict__ b_hh,
               const float* __restrict__ W1, const float* __restrict__ b1v,
               const float* __restrict__ W2, const float* __restrict__ b2v,
               float* __restrict__ out)
{
  __shared__ __align__(16) float buf[2][2][BUFW];   // [parity][batch][windowed K-vector]
  __shared__ __align__(8)  float cpart[2][2][64];   // count partials, gathered at rank 0

  const int tid  = threadIdx.x;
  const int lane = tid & 31;
  const int warp = tid >> 5;
  const int q8   = tid & 7;
  const int rs   = tid >> 3;
  const int crank = blockIdx.x & 7;
  const int cid   = blockIdx.x >> 3;

  int len0 = lengths[cid*2];
  int len1 = lengths[cid*2+1];
  len0 = min(max(len0,0),Tt); len1 = min(max(len1,0),Tt);
  const int Lmax = max(len0,len1);

  const int r0 = crank*64 + rs*2;     // this thread's global rows r0, r0+1

  // ---- load weights into registers as f32x2 pairs (80 regs per row) ----
  u64t wp0[40], wp1[40];
#pragma unroll
  for (int i=0;i<40;i++){
    const int k = q8*WINW + 2*i;
    const float* p0 = (k < Hh) ? (W_hh + (size_t)r0*Hh + k)     : (W_ih + (size_t)r0*Ff + (k-Hh));
    const float* p1 = (k < Hh) ? (W_hh + (size_t)(r0+1)*Hh + k) : (W_ih + (size_t)(r0+1)*Ff + (k-Hh));
    wp0[i] = *reinterpret_cast<const u64t*>(p0);
    wp1[i] = *reinterpret_cast<const u64t*>(p1);
  }

  // ---- per-row bias and collapsed FC vector v = W1^T W2^T ----
  float bias0=0.f, bias1=0.f, v0=0.f, v1=0.f;
  if (q8==0){
    bias0 = b_ih[r0]   + b_hh[r0];
    bias1 = b_ih[r0+1] + b_hh[r0+1];
    for (int j=0;j<Ff;j++){
      float w2j = W2[j];
      v0 = fmaf(w2j, W1[(size_t)j*Hh + r0],     v0);
      v1 = fmaf(w2j, W1[(size_t)j*Hh + r0 + 1], v1);
    }
  }
  float cc = 0.f;  // c = W2.b1 + b2 (only needed by rank0 warps 0/1 lane 0)
  if (crank==0 && warp<2 && lane==0){
    cc = b2v[0];
    for (int j=0;j<Ff;j++) cc = fmaf(W2[j], b1v[j], cc);
  }

  // ---- zero smem (h0 = 0), stage x(0) into buf[0] ----
  for (int i=tid;i<2*2*BUFW;i+=256) (&buf[0][0][0])[i]=0.f;
  for (int i=tid;i<256;i+=256)      (&cpart[0][0][0])[i]=0.f;
  __syncthreads();
  if (warp>=6){
    const int b  = warp-6;
    const int i4 = lane*4;
    float4 xv = *reinterpret_cast<const float4*>(x + ((size_t)(cid*2+b)*Tt + 0)*Ff + i4);
    const int a = (i4<48)?(6*WPAD+32+i4):(7*WPAD+(i4-48));   // x lives in windows 6/7
    *reinterpret_cast<float4*>(&buf[0][b][a]) = xv;
  }

  // DSMEM base addresses of all 8 CTAs' buffers
  const uint32_t mybuf = smem_u32(&buf[0][0][0]);
  uint32_t dsm[8];
#pragma unroll
  for (int c=0;c<8;c++) dsm[c] = mapa_u32(mybuf, (uint32_t)c);
  const uint32_t cp0 = mapa_u32(smem_u32(&cpart[0][0][0]), 0u);
  const int kaddr = (r0/WINW)*WPAD + (r0%WINW);  // windowed address of row pair (even -> 8B aligned)

  float cnt = 0.f;   // valid at crank0, warp0 lane0 (batch 0), warp1 lane0 (batch 1)

  cluster_sync_all();

  for (int t=0; t<Lmax; t++){
    const int p = t & 1;

    // ---- prefetch x(t+1) (warps 6/7), hidden under FMA block ----
    float4 xv; int xgo = 0; int xb = 0;
    if (warp>=6){
      xb = warp-6;
      const int lx = xb ? len1 : len0;
      if (t+1 < lx){
        xgo = 1;
        xv = *reinterpret_cast<const float4*>(x + ((size_t)(cid*2+xb)*Tt + (t+1))*Ff + lane*4);
      }
    }

    // ---- rank0 warps 0/1: finish count for step t-1 (partials synced last step) ----
    if (crank==0 && warp<2 && t>=1){
      const int lw = warp ? len1 : len0;
      if ((t-1) < lw){
        float s = cpart[p][warp][lane*2] + cpart[p][warp][lane*2+1];
        s += __shfl_xor_sync(0xffffffffu, s, 1);
        s += __shfl_xor_sync(0xffffffffu, s, 2);
        s += __shfl_xor_sync(0xffffffffu, s, 4);
        s += __shfl_xor_sync(0xffffffffu, s, 8);
        s += __shfl_xor_sync(0xffffffffu, s, 16);
        if (lane==0 && (s + cc) > 0.f) cnt += 1.f;
      }
    }

    // ---- recurrence GEMV for each batch ----
#pragma unroll
    for (int b=0;b<2;b++){
      const int lb = b ? len1 : len0;
      if (t < lb){
        const ulonglong2* kv = reinterpret_cast<const ulonglong2*>(&buf[p][b][q8*WPAD]);
        u64t a0=0,a1=0,a2=0,a3=0;
#pragma unroll
        for (int i=0;i<20;i++){
          ulonglong2 kk = kv[i];                 // LDS.128: 4 K-values, broadcast to 4 row-pairs
          FMA2(a0, wp0[2*i],   kk.x, a0);
          FMA2(a1, wp0[2*i+1], kk.y, a1);
          FMA2(a2, wp1[2*i],   kk.x, a2);
          FMA2(a3, wp1[2*i+1], kk.y, a3);
        }
        float2 f0=unpack2(a0), f1=unpack2(a1), f2=unpack2(a2), f3=unpack2(a3);
        float s0 = (f0.x+f0.y)+(f1.x+f1.y);
        float s1 = (f2.x+f2.y)+(f3.x+f3.y);
        // reduce across the 8 K-windows (lanes q8=0..7 of each group)
        s0 += __shfl_xor_sync(0xffffffffu, s0, 1);
        s0 += __shfl_xor_sync(0xffffffffu, s0, 2);
        s0 += __shfl_xor_sync(0xffffffffu, s0, 4);
        s1 += __shfl_xor_sync(0xffffffffu, s1, 1);
        s1 += __shfl_xor_sync(0xffffffffu, s1, 2);
        s1 += __shfl_xor_sync(0xffffffffu, s1, 4);

        float pc = 0.f;
        u64t  hv = 0;
        if (q8==0){
          float h0 = tanhf(s0 + bias0);
          float h1 = tanhf(s1 + bias1);
          hv = pack2(h0,h1);
          pc = fmaf(v0, h0, v1*h1);              // count-dot partial for these 2 rows
        }
        pc += __shfl_xor_sync(0xffffffffu, pc, 8);
        pc += __shfl_xor_sync(0xffffffffu, pc, 16);

        const uint32_t off = (uint32_t)(((((p^1)*2)+b)*BUFW + kaddr)*4);
        if (q8==0){
#pragma unroll
          for (int c=0;c<8;c++) stc64(dsm[c]+off, hv);   // broadcast h pair to whole cluster
        }
        if (lane==0)
          stc32(cp0 + (uint32_t)(((((p^1)*2)+b)*64 + crank*8 + warp)*4), pc);
      } else if (t == lb){
        // freeze fixup: copy frozen h into the other parity buffer once; both stay valid forever
        if (q8==0){
          u64t hv = *reinterpret_cast<const u64t*>(&buf[p][b][kaddr]);
          const uint32_t off = (uint32_t)(((((p^1)*2)+b)*BUFW + kaddr)*4);
#pragma unroll
          for (int c=0;c<8;c++) stc64(dsm[c]+off, hv);
        }
      }
    }

    // ---- stage prefetched x(t+1) into next-parity buffer (local STS) ----
    if (xgo){
      const int i4 = lane*4;
      const int a = (i4<48)?(6*WPAD+32+i4):(7*WPAD+(i4-48));
      *reinterpret_cast<float4*>(&buf[p^1][xb][a]) = xv;
    }

    cluster_sync_all();   // release h/partial stores, one sync per step (double-buffered)
  }

  // ---- epilogue (rank 0 of each cluster) ----
  const int fb = Lmax & 1;   // final h lives in buf[fb]
  if (crank==0){
    if (warp<2){
      const int b  = warp;
      const int lb = b ? len1 : len0;
      float s = cpart[fb][b][lane*2] + cpart[fb][b][lane*2+1];
      s += __shfl_xor_sync(0xffffffffu, s, 1);
      s += __shfl_xor_sync(0xffffffffu, s, 2);
      s += __shfl_xor_sync(0xffffffffu, s, 4);
      s += __shfl_xor_sync(0xffffffffu, s, 8);
      s += __shfl_xor_sync(0xffffffffu, s, 16);
      if (lane==0){
        if ((Lmax-1) < lb && (s + cc) > 0.f) cnt += 1.f;  // count for the last step
        out[cid*2 + b] = cnt;
      }
    }
#pragma unroll 1
    for (int b=0;b<2;b++){
      for (int k=tid;k<Hh;k+=256){
        const int a = (k/WINW)*WPAD + (k%WINW);
        out[Bb + (size_t)(cid*2+b)*Hh + k] = buf[fb][b][a];
      }
    }
  }
}

extern "C" void kernel_launch(void* const* d_in, const int* in_sizes, int n_in,
                              void* d_out, int out_size) {
  const float* x       = (const float*)d_in[0];
  const int*   lengths = (const int*)  d_in[1];
  const float* W_ih    = (const float*)d_in[2];
  const float* W_hh    = (const float*)d_in[3];
  const float* b_ih    = (const float*)d_in[4];
  const float* b_hh    = (const float*)d_in[5];
  const float* W1      = (const float*)d_in[6];
  const float* b1      = (const float*)d_in[7];
  const float* W2      = (const float*)d_in[8];
  const float* b2      = (const float*)d_in[9];
  rnn_enc_kernel<<<128, 256>>>(x, lengths, W_ih, W_hh, b_ih, b_hh, W1, b1, W2, b2, (float*)d_out);
}

// round 4
// speedup vs baseline: 1.2859x; 1.2859x over previous
#include <cuda_runtime.h>
#include <cuda_bf16.h>
#include <cstdint>
#include <cstddef>

typedef unsigned long long u64t;

#define Bb 32
#define Tt 2048
#define Ff 128
#define Hh 512
#define WINW 80          // words per K-window
#define WPAD 84          // padded stride (bank stagger)
#define BUFW (8*WPAD)    // 672 words per (parity,batch) K-vector [h(512) | x(128)]

__device__ __forceinline__ uint32_t smem_u32(const void* p){
  uint32_t a; asm("{ .reg .u64 t; cvta.to.shared.u64 t, %1; cvt.u32.u64 %0, t; }" : "=r"(a) : "l"(p)); return a;
}
__device__ __forceinline__ uint32_t mapa_u32(uint32_t a, uint32_t r){
  uint32_t d; asm("mapa.shared::cluster.u32 %0, %1, %2;" : "=r"(d) : "r"(a), "r"(r)); return d;
}
__device__ __forceinline__ void stc64(uint32_t a, u64t v){
  asm volatile("st.shared::cluster.u64 [%0], %1;" :: "r"(a), "l"(v) : "memory");
}
__device__ __forceinline__ void stc32(uint32_t a, float v){
  asm volatile("st.shared::cluster.f32 [%0], %1;" :: "r"(a), "f"(v) : "memory");
}
__device__ __forceinline__ void cluster_sync_all(){
  asm volatile("barrier.cluster.arrive.aligned;" ::: "memory");
  asm volatile("barrier.cluster.wait.aligned;" ::: "memory");
}
__device__ __forceinline__ void mbar_init(uint32_t a, uint32_t cnt){
  asm volatile("mbarrier.init.shared.b64 [%0], %1;" :: "r"(a), "r"(cnt) : "memory");
}
__device__ __forceinline__ void mbar_arrive_cluster(uint32_t ra){
  asm volatile("mbarrier.arrive.shared::cluster.b64 _, [%0];" :: "r"(ra) : "memory");
}
__device__ __forceinline__ void mbar_wait(uint32_t a, uint32_t parity){
  asm volatile(
    "{\n\t.reg .pred P;\n\t"
    "MW_%=:\n\t"
    "mbarrier.try_wait.parity.acquire.cluster.shared::cta.b64 P, [%0], %1, 0x989680;\n\t"
    "@P bra.uni MD_%=;\n\t"
    "bra.uni MW_%=;\n\t"
    "MD_%=:\n\t}"
    :: "r"(a), "r"(parity) : "memory");
}
#define FMA2(d,a,b,c) asm("fma.rn.f32x2 %0, %1, %2, %3;" : "=l"(d) : "l"(a), "l"(b), "l"(c))
__device__ __forceinline__ float2 unpack2(u64t v){
  float2 r; asm("mov.b64 {%0,%1}, %2;" : "=f"(r.x), "=f"(r.y) : "l"(v)); return r;
}
__device__ __forceinline__ u64t pack2(float lo, float hi){
  u64t r; asm("mov.b64 %0, {%1,%2};" : "=l"(r) : "f"(lo), "f"(hi)); return r;
}
__device__ __forceinline__ float fast_tanh(float xx){
  float ax = fabsf(xx);
  float e  = __expf(-2.0f * ax);
  float r  = __fdividef(1.0f - e, 1.0f + e);
  return copysignf(r, xx);
}

// 16 clusters of 8 CTAs; cluster c handles batches 2c, 2c+1.
// CTA (rank) holds rows [rank*64, rank*64+64) of W = [W_hh | W_ih] (640 cols) in registers.
// Thread (rs=tid>>3, q8=tid&7): rows 2rs, 2rs+1; K-window [q8*80, q8*80+80).
// Per-step protocol: wait(mbar[p]) -> read buf[p] -> compute -> store h/cpart to
// buf[p^1] of rank q8 -> __syncthreads -> arrive mbar[p^1] of rank q8 (count 256).
__global__ void __launch_bounds__(256,1) __cluster_dims__(8,1,1)
rnn_enc_kernel(const float* __restrict__ x, const int* __restrict__ lengths,
               const float* __restrict__ W_ih, const float* __restrict__ W_hh,
               const float* __restrict__ b_ih, const float* __restrict__ b_hh,
               const float* __restrict__ W1, const float* __restrict__ b1v,
               const float* __restrict__ W2, const float* __restrict__ b2v,
               float* __restrict__ out)
{
  __shared__ __align__(16) float buf[2][2][BUFW];   // [parity][batch][windowed K-vector]
  __shared__ __align__(8)  float cpart[2][2][64];   // count partials, gathered at rank 0
  __shared__ __align__(8)  u64t  mbar[2];           // parity barriers

  const int tid  = threadIdx.x;
  const int lane = tid & 31;
  const int warp = tid >> 5;
  const int q8   = tid & 7;
  const int rs   = tid >> 3;
  const int crank = blockIdx.x & 7;
  const int cid   = blockIdx.x >> 3;

  int len0 = lengths[cid*2];
  int len1 = lengths[cid*2+1];
  len0 = min(max(len0,0),Tt); len1 = min(max(len1,0),Tt);
  const int Lmax = max(len0,len1);

  const int r0 = crank*64 + rs*2;     // this thread's global rows r0, r0+1

  // ---- load weights into registers as f32x2 pairs (80 regs per row) ----
  u64t wp0[40], wp1[40];
#pragma unroll
  for (int i=0;i<40;i++){
    const int k = q8*WINW + 2*i;
    const float* p0 = (k < Hh) ? (W_hh + (size_t)r0*Hh + k)     : (W_ih + (size_t)r0*Ff + (k-Hh));
    const float* p1 = (k < Hh) ? (W_hh + (size_t)(r0+1)*Hh + k) : (W_ih + (size_t)(r0+1)*Ff + (k-Hh));
    wp0[i] = *reinterpret_cast<const u64t*>(p0);
    wp1[i] = *reinterpret_cast<const u64t*>(p1);
  }

  // ---- per-row bias and collapsed FC vector v = W1^T W2^T (all lanes) ----
  float bias0 = b_ih[r0]   + b_hh[r0];
  float bias1 = b_ih[r0+1] + b_hh[r0+1];
  float v0=0.f, v1=0.f;
  for (int j=0;j<Ff;j++){
    float w2j = W2[j];
    v0 = fmaf(w2j, W1[(size_t)j*Hh + r0],     v0);
    v1 = fmaf(w2j, W1[(size_t)j*Hh + r0 + 1], v1);
  }
  float cc = 0.f;  // c = W2.b1 + b2 (only used by rank0 warps 0/1 lane 0)
  if (crank==0 && warp<2 && lane==0){
    cc = b2v[0];
    for (int j=0;j<Ff;j++) cc = fmaf(W2[j], b1v[j], cc);
  }

  // ---- zero smem (h0 = 0), init barriers, stage x(0) into buf[0] ----
  for (int i=tid;i<2*2*BUFW;i+=256) (&buf[0][0][0])[i]=0.f;
  for (int i=tid;i<256;i+=256)      (&cpart[0][0][0])[i]=0.f;
  const uint32_t lmb = smem_u32(&mbar[0]);
  if (tid==0){ mbar_init(lmb, 256u); mbar_init(lmb+8u, 256u); }
  __syncthreads();
  if (warp>=6){
    const int b  = warp-6;
    const int i4 = lane*4;
    float4 xv = *reinterpret_cast<const float4*>(x + ((size_t)(cid*2+b)*Tt + 0)*Ff + i4);
    const int a = (i4<48)?(6*WPAD+32+i4):(7*WPAD+(i4-48));   // x lives in windows 6/7
    *reinterpret_cast<float4*>(&buf[0][b][a]) = xv;
  }
  __syncthreads();

  const uint32_t mybuf = smem_u32(&buf[0][0][0]);
  const uint32_t dsmq  = mapa_u32(mybuf, (uint32_t)q8);        // rank q8's buf base
  const uint32_t rmb   = mapa_u32(lmb,   (uint32_t)q8);        // rank q8's barriers
  const uint32_t cp0   = mapa_u32(smem_u32(&cpart[0][0][0]), 0u);
  const int kaddr = (r0/WINW)*WPAD + (r0%WINW);  // windowed address of row pair

  float cnt = 0.f;        // valid at crank0, warp{0,1} lane0
  uint32_t ph0=0, ph1=0;  // wait-phase per parity barrier
  const int lw = (warp&1) ? len1 : len0;

  cluster_sync_all();     // barriers + initial buffers visible cluster-wide

  for (int t=0; t<Lmax; t++){
    const int p = t & 1;

    // ---- x(t+1) LDG prefetch first: independent of the barrier ----
    float4 xv; int xgo = 0; int xb = 0;
    if (warp>=6){
      xb = warp-6;
      const int lx = xb ? len1 : len0;
      if (t+1 < lx){
        xgo = 1;
        xv = *reinterpret_cast<const float4*>(x + ((size_t)(cid*2+xb)*Tt + (t+1))*Ff + lane*4);
      }
    }

    // ---- wait for buf[p]/cpart[p] complete ----
    if (t > 0){
      uint32_t par = p ? ph1 : ph0;
      mbar_wait(lmb + (uint32_t)(p*8), par);
      if (p) ph1 ^= 1u; else ph0 ^= 1u;
    }

    // snapshot count partials early (step t+1 may overwrite cpart[p])
    const bool do_cnt = (crank==0) && (warp<2) && (t>=1) && ((t-1) < lw);
    float cpa=0.f, cpb=0.f;
    if (do_cnt){ cpa = cpart[p][warp][lane*2]; cpb = cpart[p][warp][lane*2+1]; }

    // ---- recurrence GEMV for each batch ----
#pragma unroll
    for (int b=0;b<2;b++){
      const int lb = b ? len1 : len0;
      const uint32_t off = (uint32_t)(((((p^1)*2)+b)*BUFW + kaddr)*4);
      if (t < lb){
        const ulonglong2* kvp = reinterpret_cast<const ulonglong2*>(&buf[p][b][q8*WPAD]);
        ulonglong2 r0k=kvp[0], r1k=kvp[1], r2k=kvp[2], r3k=kvp[3];
        u64t a0=0,a1=0,a2=0,a3=0;
#pragma unroll
        for (int g=0; g<5; g++){
          ulonglong2 n0k=r0k, n1k=r1k, n2k=r2k, n3k=r3k;
          if (g<4){ n0k=kvp[4*g+4]; n1k=kvp[4*g+5]; n2k=kvp[4*g+6]; n3k=kvp[4*g+7]; }
          const int i0 = 8*g;
          FMA2(a0, wp0[i0+0], r0k.x, a0);
          FMA2(a1, wp0[i0+1], r0k.y, a1);
          FMA2(a2, wp1[i0+0], r0k.x, a2);
          FMA2(a3, wp1[i0+1], r0k.y, a3);
          FMA2(a0, wp0[i0+2], r1k.x, a0);
          FMA2(a1, wp0[i0+3], r1k.y, a1);
          FMA2(a2, wp1[i0+2], r1k.x, a2);
          FMA2(a3, wp1[i0+3], r1k.y, a3);
          FMA2(a0, wp0[i0+4], r2k.x, a0);
          FMA2(a1, wp0[i0+5], r2k.y, a1);
          FMA2(a2, wp1[i0+4], r2k.x, a2);
          FMA2(a3, wp1[i0+5], r2k.y, a3);
          FMA2(a0, wp0[i0+6], r3k.x, a0);
          FMA2(a1, wp0[i0+7], r3k.y, a1);
          FMA2(a2, wp1[i0+6], r3k.x, a2);
          FMA2(a3, wp1[i0+7], r3k.y, a3);
          r0k=n0k; r1k=n1k; r2k=n2k; r3k=n3k;
        }
        float2 f0=unpack2(a0), f1=unpack2(a1), f2=unpack2(a2), f3=unpack2(a3);
        float s0 = (f0.x+f0.y)+(f1.x+f1.y);
        float s1 = (f2.x+f2.y)+(f3.x+f3.y);
        // butterfly across the 8 K-windows: ALL lanes end with the full sums
        s0 += __shfl_xor_sync(0xffffffffu, s0, 1);
        s1 += __shfl_xor_sync(0xffffffffu, s1, 1);
        s0 += __shfl_xor_sync(0xffffffffu, s0, 2);
        s1 += __shfl_xor_sync(0xffffffffu, s1, 2);
        s0 += __shfl_xor_sync(0xffffffffu, s0, 4);
        s1 += __shfl_xor_sync(0xffffffffu, s1, 4);

        float h0 = fast_tanh(s0 + bias0);
        float h1 = fast_tanh(s1 + bias1);
        // lane q8=c broadcasts this row pair to rank c (1 store per lane)
        stc64(dsmq + off, pack2(h0,h1));

        float pc = fmaf(v0, h0, v1*h1);
        pc += __shfl_xor_sync(0xffffffffu, pc, 8);
        pc += __shfl_xor_sync(0xffffffffu, pc, 16);
        if (lane==0)
          stc32(cp0 + (uint32_t)(((((p^1)*2)+b)*64 + crank*8 + warp)*4), pc);
      } else if (t == lb){
        // freeze fixup: copy frozen h into the other parity buffer once
        u64t hv = *reinterpret_cast<const u64t*>(&buf[p][b][kaddr]);
        stc64(dsmq + off, hv);
      }
    }

    // ---- stage prefetched x(t+1) into next-parity buffer (local STS) ----
    if (xgo){
      const int i4 = lane*4;
      const int a = (i4<48)?(6*WPAD+32+i4):(7*WPAD+(i4-48));
      *reinterpret_cast<float4*>(&buf[p^1][xb][a]) = xv;
    }

    // ---- CTA-wide read/exec fence, then per-lane release-arrive ----
    __syncthreads();
    mbar_arrive_cluster(rmb + (uint32_t)((p^1)*8));

    // ---- rank0 warps 0/1: finish count for step t-1 (off critical path) ----
    if (do_cnt){
      float s = cpa + cpb;
      s += __shfl_xor_sync(0xffffffffu, s, 1);
      s += __shfl_xor_sync(0xffffffffu, s, 2);
      s += __shfl_xor_sync(0xffffffffu, s, 4);
      s += __shfl_xor_sync(0xffffffffu, s, 8);
      s += __shfl_xor_sync(0xffffffffu, s, 16);
      if (lane==0 && (s + cc) > 0.f) cnt += 1.f;
    }
  }

  // ---- final wait: all stores/arrives for the last step have landed ----
  const int fb = Lmax & 1;
  {
    uint32_t par = fb ? ph1 : ph0;
    mbar_wait(lmb + (uint32_t)(fb*8), par);
  }

  // ---- epilogue (rank 0 of each cluster) ----
  if (crank==0){
    if (warp<2){
      const int b  = warp;
      const int lb = b ? len1 : len0;
      float s = cpart[fb][b][lane*2] + cpart[fb][b][lane*2+1];
      s += __shfl_xor_sync(0xffffffffu, s, 1);
      s += __shfl_xor_sync(0xffffffffu, s, 2);
      s += __shfl_xor_sync(0xffffffffu, s, 4);
      s += __shfl_xor_sync(0xffffffffu, s, 8);
      s += __shfl_xor_sync(0xffffffffu, s, 16);
      if (lane==0){
        if ((Lmax-1) < lb && (s + cc) > 0.f) cnt += 1.f;  // last step's count
        out[cid*2 + b] = cnt;
      }
    }
#pragma unroll 1
    for (int b=0;b<2;b++){
      for (int k=tid;k<Hh;k+=256){
        const int a = (k/WINW)*WPAD + (k%WINW);
        out[Bb + (size_t)(cid*2+b)*Hh + k] = buf[fb][b][a];
      }
    }
  }
}

extern "C" void kernel_launch(void* const* d_in, const int* in_sizes, int n_in,
                              void* d_out, int out_size) {
  const float* x       = (const float*)d_in[0];
  const int*   lengths = (const int*)  d_in[1];
  const float* W_ih    = (const float*)d_in[2];
  const float* W_hh    = (const float*)d_in[3];
  const float* b_ih    = (const float*)d_in[4];
  const float* b_hh    = (const float*)d_in[5];
  const float* W1      = (const float*)d_in[6];
  const float* b1      = (const float*)d_in[7];
  const float* W2      = (const float*)d_in[8];
  const float* b2      = (const float*)d_in[9];
  rnn_enc_kernel<<<128, 256>>>(x, lengths, W_ih, W_hh, b_ih, b_hh, W1, b1, W2, b2, (float*)d_out);
}